// round 10
// baseline (speedup 1.0000x reference)
#include <cuda_runtime.h>

#define BB   128
#define LL   131072
#define TT   4096
#define HIST 64
#define WIN  32
#define DIMS 32
#define NP   16

#define SEGC   32             // output steps per segment
#define SEGW   96             // warmup steps (rel_err ~3.7e-4, 2.7x margin)
#define NSEG   (TT / SEGC)    // 128

typedef unsigned long long u64;

// Scores [t][b][16]; padded for scan prefetch overrun (4*BB*NP + slack).
__device__ float  g_scores[(size_t)TT * BB * NP + 16384];
// params [t][b]
__device__ float2 g_params[(size_t)TT * BB];

__device__ __forceinline__ float ex2f(float x) {
    float r; asm("ex2.approx.f32 %0, %1;" : "=f"(r) : "f"(x)); return r;
}
__device__ __forceinline__ float rcpf(float x) {
    float r; asm("rcp.approx.f32 %0, %1;" : "=f"(r) : "f"(x)); return r;
}
__device__ __forceinline__ u64 pack2(float lo, float hi) {
    u64 r; asm("mov.b64 %0, {%1, %2};" : "=l"(r) : "f"(lo), "f"(hi)); return r;
}
__device__ __forceinline__ void unpack2(u64 v, float& lo, float& hi) {
    asm("mov.b64 {%0, %1}, %2;" : "=f"(lo), "=f"(hi) : "l"(v));
}
__device__ __forceinline__ u64 ffma2(u64 a, u64 b, u64 c) {
    u64 d; asm("fma.rn.f32x2 %0, %1, %2, %3;" : "=l"(d) : "l"(a), "l"(b), "l"(c));
    return d;
}

// ---------------------------------------------------------------------------
// Kernel A: conv + relu + key projection, FFMA2, 256 threads/block.
// x staged in padded-linear layout: sx2[36*(j>>5) + (j&31)] = xpad[j],
// j = t*32 + h. A tap-group (hb, hb+1..hb+3), hb%4==0, for one t is ONE
// aligned LDS.128 (never crosses a pad). Conv-core LDS/thread: 384 -> 192.
// Projection register-blocked as in R9 (unchanged).
// ---------------------------------------------------------------------------
#define TTA 256
#define SXB_STRIDE 36         // floats per 32-float block (pad 4)
#define SXB_COUNT  258        // ceil(8256/32) blocks
#define SPJ_STRIDE 34         // [t][d] pad; even for 8B-aligned u64 stores
#define SBUF_FL    (SXB_STRIDE * SXB_COUNT)   // 9288 >= 256*34=8704

__global__ void __launch_bounds__(256)
conv_scores_kernel(const float* __restrict__ x,
                   const float* __restrict__ conv_w,
                   const float* __restrict__ conv_b,
                   const float* __restrict__ keys)
{
    __shared__ __align__(16) float sbuf[SBUF_FL];     // sx2, then proj buffer
    __shared__ __align__(16) float sw2[HIST * DIMS];  // [h][d]
    __shared__ __align__(16) float skb[DIMS * NP];    // [d][p]
    __shared__ __align__(16) float sb[DIMS];

    const int b    = blockIdx.y;
    const int tile = blockIdx.x;
    const int tid  = threadIdx.x;
    const int wid  = tid >> 5;
    const int lane = tid & 31;
    const int dg   = wid & 3;    // per-warp d-group (8 d)
    const int th   = wid >> 2;   // t-half

    // ---- stage x padded-linear: j in [0,8256), value = xb[tile*8192 + j - 63]
    {
        const long gbase = (long)tile * (TTA * WIN) - 63;
        const float* xb = x + (size_t)b * LL;
        for (int j = tid; j < TTA * WIN + HIST; j += 256) {
            const long g = gbase + j;
            sbuf[SXB_STRIDE * (j >> 5) + (j & 31)] =
                (g >= 0 && g < LL) ? xb[g] : 0.f;
        }
        for (int i = tid; i < HIST * DIMS; i += 256) {
            const int d = i & 31, h = i >> 5;
            sw2[h * DIMS + d] = conv_w[d * HIST + h];
        }
        for (int i = tid; i < DIMS * NP; i += 256) skb[i] = keys[i];
        if (tid < DIMS) sb[tid] = conv_b[tid];
    }
    __syncthreads();

    const int dbase = dg * 8;
    const int tbase = th * 128 + lane;   // + 32*tt, tt=0..3

    // acc[tt][k]: f32x2 over (d=dbase+2k, d+1), init with bias
    u64 acc[4][4];
    {
        const float2* bp = (const float2*)&sb[dbase];
#pragma unroll
        for (int k = 0; k < 4; k++) {
            const float2 bv = bp[k];
            const u64 bi = pack2(bv.x, bv.y);
#pragma unroll
            for (int tt = 0; tt < 4; tt++) acc[tt][k] = bi;
        }
    }

    // 16 tap-groups of 4: hb = 4g. x4(t) = xpad[t*32+hb .. +4) as one LDS.128.
#pragma unroll 2
    for (int g = 0; g < 16; g++) {
        const int hb   = g * 4;
        const int blk0 = hb >> 5;       // 0 or 1
        const int off  = hb & 31;       // multiple of 4
        float4 x4[4];
#pragma unroll
        for (int tt = 0; tt < 4; tt++) {
            const int t = tbase + 32 * tt;
            x4[tt] = *(const float4*)&sbuf[SXB_STRIDE * (t + blk0) + off];
        }
#pragma unroll
        for (int k = 0; k < 4; k++) {   // taps hb+k
            const int h = hb + k;
            const ulonglong2* wp = (const ulonglong2*)&sw2[h * DIMS + dbase];
            const ulonglong2 wa = wp[0], wb = wp[1];
#pragma unroll
            for (int tt = 0; tt < 4; tt++) {
                const float xv = (k == 0) ? x4[tt].x : (k == 1) ? x4[tt].y
                               : (k == 2) ? x4[tt].z : x4[tt].w;
                const u64 xd = pack2(xv, xv);
                acc[tt][0] = ffma2(xd, wa.x, acc[tt][0]);
                acc[tt][1] = ffma2(xd, wa.y, acc[tt][1]);
                acc[tt][2] = ffma2(xd, wb.x, acc[tt][2]);
                acc[tt][3] = ffma2(xd, wb.y, acc[tt][3]);
            }
        }
    }

    // ---- dump conv result (pre-relu) to sproj[t][d] (reusing sbuf)
    __syncthreads();   // all x reads done before overwrite
    {
        u64* sp64 = (u64*)sbuf;
#pragma unroll
        for (int tt = 0; tt < 4; tt++) {
            const int t = tbase + 32 * tt;
#pragma unroll
            for (int k = 0; k < 4; k++)
                sp64[(t * SPJ_STRIDE + dbase) / 2 + k] = acc[tt][k];
        }
    }
    __syncthreads();   // row t assembled from 4 warps

    // ---- projection: 128 threads, thread = (q, ph) computes 4t x 8p tile.
    if (tid < 128) {
        const int q  = tid >> 1;     // 0..63
        const int ph = tid & 1;      // p-half
        u64 pa[4][4];
#pragma unroll
        for (int i = 0; i < 4; i++)
#pragma unroll
            for (int j = 0; j < 4; j++) pa[i][j] = 0ull;

#pragma unroll 4
        for (int d = 0; d < DIMS; d++) {
            const u64* kp = (const u64*)&skb[d * NP + ph * 8];
            const u64 k0 = kp[0], k1 = kp[1], k2 = kp[2], k3 = kp[3];
#pragma unroll
            for (int i = 0; i < 4; i++) {
                const int t = q + 64 * i;
                const float oa = fmaxf(sbuf[t * SPJ_STRIDE + d], 0.f);
                const u64 o2 = pack2(oa, oa);
                pa[i][0] = ffma2(o2, k0, pa[i][0]);
                pa[i][1] = ffma2(o2, k1, pa[i][1]);
                pa[i][2] = ffma2(o2, k2, pa[i][2]);
                pa[i][3] = ffma2(o2, k3, pa[i][3]);
            }
        }

        const float L2E = 1.4426950408889634f;
#pragma unroll
        for (int i = 0; i < 4; i++) {
            const int gt = tile * TTA + q + 64 * i;
            float4* dst = (float4*)(g_scores + ((size_t)gt * BB + b) * NP + ph * 8);
#pragma unroll
            for (int v = 0; v < 2; v++) {
                float p0, p1, p2, p3;
                unpack2(pa[i][v * 2 + 0], p0, p1);
                unpack2(pa[i][v * 2 + 1], p2, p3);
                float4 o;
                o.x = fminf(fmaxf(p0, 0.f), 6.f) * L2E;
                o.y = fminf(fmaxf(p1, 0.f), 6.f) * L2E;
                o.z = fminf(fmaxf(p2, 0.f), 6.f) * L2E;
                o.w = fminf(fmaxf(p3, 0.f), 6.f) * L2E;
                dst[v] = o;
            }
        }
    }
}

// ---------------------------------------------------------------------------
// Kernel B: shfl-free chunked scan (SEGW=96, SEGC=32; 512 warps).
// ---------------------------------------------------------------------------
struct ScanState {
    float  A[NP];
    float  pp[NP];
    float  qmb[NP];
    float4 qc[4][4];
};

template<bool OUT>
__device__ __forceinline__ void scan_step(int k, int t, int b, ScanState& S,
                                          const float4* __restrict__ sp,
                                          const float* s0, const float* s1,
                                          float2* __restrict__ prm)
{
    const float L2E = 1.4426950408889634f;
    float e[NP];
#pragma unroll
    for (int i = 0; i < NP; i++)
        e[i] = ex2f(fmaf(S.pp[i], -L2E, S.qmb[i]));

    const size_t pbase = ((size_t)(t + 4) * BB + (size_t)b) * 4;
    float4 v0 = sp[pbase + 0], v1 = sp[pbase + 1],
           v2 = sp[pbase + 2], v3 = sp[pbase + 3];

#pragma unroll
    for (int i = 0; i < NP; i++)
        S.A[i] = fmaf(S.pp[i], L2E, S.A[i]);

    float ss = ((((e[0] + e[1]) + (e[2] + e[3])) + ((e[4] + e[5]) + (e[6] + e[7])))
             + (((e[8] + e[9]) + (e[10] + e[11])) + ((e[12] + e[13]) + (e[14] + e[15]))));
    float r = rcpf(ss);

    float d0, d1;
    if (OUT) {
        float a0 = 0.f, a1 = 0.f, b0 = 0.f, b1 = 0.f;
#pragma unroll
        for (int i = 0; i < NP; i += 2) {
            a0 = fmaf(e[i],     s0[i],     a0);
            b0 = fmaf(e[i + 1], s0[i + 1], b0);
            a1 = fmaf(e[i],     s1[i],     a1);
            b1 = fmaf(e[i + 1], s1[i + 1], b1);
        }
        d0 = a0 + b0; d1 = a1 + b1;
    }

#pragma unroll
    for (int i = 0; i < NP; i++) S.pp[i] = e[i] * r;

    S.qc[k][0] = v0; S.qc[k][1] = v1; S.qc[k][2] = v2; S.qc[k][3] = v3;

    const int kn = (k + 1) & 3;
#pragma unroll
    for (int j = 0; j < 4; j++) {
        const float4 n = S.qc[kn][j];
        S.qmb[j * 4 + 0] = n.x - S.A[j * 4 + 0];
        S.qmb[j * 4 + 1] = n.y - S.A[j * 4 + 1];
        S.qmb[j * 4 + 2] = n.z - S.A[j * 4 + 2];
        S.qmb[j * 4 + 3] = n.w - S.A[j * 4 + 3];
    }

    if (OUT) prm[(size_t)t * BB + b] = make_float2(d0 * r, d1 * r);
}

__global__ void __launch_bounds__(32)
scan_kernel(const float* __restrict__ avg0, const float* __restrict__ shapes)
{
    const int lane = threadIdx.x;
    const int seg  = blockIdx.x >> 2;
    const int b    = (blockIdx.x & 3) * 32 + lane;

    const int s_start = seg * SEGC;
    const int t0 = (s_start >= SEGW) ? (s_start - SEGW) : 0;

    const float L2E = 1.4426950408889634f;
    const float4* sp = (const float4*)g_scores;
    float2* prm = g_params;

    ScanState S;
#pragma unroll
    for (int i = 0; i < NP; i++) {
        S.A[i]  = avg0[b * NP + i] * L2E;
        S.pp[i] = 0.f;
    }
#pragma unroll
    for (int k = 0; k < 4; k++) {
        const size_t base = ((size_t)(t0 + k) * BB + (size_t)b) * 4;
        S.qc[k][0] = sp[base + 0]; S.qc[k][1] = sp[base + 1];
        S.qc[k][2] = sp[base + 2]; S.qc[k][3] = sp[base + 3];
    }
#pragma unroll
    for (int j = 0; j < 4; j++) {
        const float4 n = S.qc[0][j];
        S.qmb[j * 4 + 0] = n.x - S.A[j * 4 + 0];
        S.qmb[j * 4 + 1] = n.y - S.A[j * 4 + 1];
        S.qmb[j * 4 + 2] = n.z - S.A[j * 4 + 2];
        S.qmb[j * 4 + 3] = n.w - S.A[j * 4 + 3];
    }

    int t = t0;
    for (; t < s_start; t += 4) {
        scan_step<false>(0, t + 0, b, S, sp, nullptr, nullptr, prm);
        scan_step<false>(1, t + 1, b, S, sp, nullptr, nullptr, prm);
        scan_step<false>(2, t + 2, b, S, sp, nullptr, nullptr, prm);
        scan_step<false>(3, t + 3, b, S, sp, nullptr, nullptr, prm);
    }

    float s0[NP], s1[NP];
#pragma unroll
    for (int i = 0; i < NP; i++) { s0[i] = shapes[i * 2]; s1[i] = shapes[i * 2 + 1]; }

    const int s_end = s_start + SEGC;
    for (; t < s_end; t += 4) {
        scan_step<true>(0, t + 0, b, S, sp, s0, s1, prm);
        scan_step<true>(1, t + 1, b, S, sp, s0, s1, prm);
        scan_step<true>(2, t + 2, b, S, sp, s0, s1, prm);
        scan_step<true>(3, t + 3, b, S, sp, s0, s1, prm);
    }
}

// ---------------------------------------------------------------------------
// Kernel C: epilogue — out = relu(offset + noise*std - x). Memory-bound.
// ---------------------------------------------------------------------------
__global__ void __launch_bounds__(256)
epilogue_kernel(const float* __restrict__ x,
                const float* __restrict__ noise,
                float* __restrict__ out)
{
    const int b  = blockIdx.y;
    const int l4 = blockIdx.x * 256 + threadIdx.x;
    const int t  = (l4 * 4) >> 5;

    const float2 pr = g_params[(size_t)t * BB + b];
    const float4 xv = ((const float4*)(x     + (size_t)b * LL))[l4];
    const float4 nv = ((const float4*)(noise + (size_t)b * LL))[l4];

    float4 o;
    o.x = fmaxf(fmaf(nv.x, pr.y, pr.x) - xv.x, 0.f);
    o.y = fmaxf(fmaf(nv.y, pr.y, pr.x) - xv.y, 0.f);
    o.z = fmaxf(fmaf(nv.z, pr.y, pr.x) - xv.z, 0.f);
    o.w = fmaxf(fmaf(nv.w, pr.y, pr.x) - xv.w, 0.f);
    ((float4*)out)[(size_t)b * (LL / 4) + l4] = o;
}

// ---------------------------------------------------------------------------
extern "C" void kernel_launch(void* const* d_in, const int* in_sizes, int n_in,
                              void* d_out, int out_size)
{
    const float* x      = (const float*)d_in[0];
    const float* avg    = (const float*)d_in[1];
    const float* noise  = (const float*)d_in[2];
    const float* conv_w = (const float*)d_in[3];
    const float* conv_b = (const float*)d_in[4];
    const float* keys   = (const float*)d_in[5];
    const float* shapes = (const float*)d_in[6];
    float* out = (float*)d_out;

    conv_scores_kernel<<<dim3(TT / TTA, BB), 256>>>(x, conv_w, conv_b, keys);
    scan_kernel<<<NSEG * 4, 32>>>(avg, shapes);
    epilogue_kernel<<<dim3(LL / 1024, BB), 256>>>(x, noise, out);
}

// round 11
// speedup vs baseline: 1.0180x; 1.0180x over previous
#include <cuda_runtime.h>

#define BB   128
#define LL   131072
#define TT   4096
#define HIST 64
#define WIN  32
#define DIMS 32
#define NP   16

#define SEGC   16             // output steps per segment
#define SEGW   96             // warmup steps (rel_err ~3.7e-4, 2.7x margin)
#define NSEG   (TT / SEGC)    // 256

typedef unsigned long long u64;

// Scores [t][b][16]; padded for scan prefetch overrun (4*BB*NP + slack).
__device__ float  g_scores[(size_t)TT * BB * NP + 16384];
// params [t][b]
__device__ float2 g_params[(size_t)TT * BB];

__device__ __forceinline__ float ex2f(float x) {
    float r; asm("ex2.approx.f32 %0, %1;" : "=f"(r) : "f"(x)); return r;
}
__device__ __forceinline__ float rcpf(float x) {
    float r; asm("rcp.approx.f32 %0, %1;" : "=f"(r) : "f"(x)); return r;
}
__device__ __forceinline__ u64 pack2(float lo, float hi) {
    u64 r; asm("mov.b64 %0, {%1, %2};" : "=l"(r) : "f"(lo), "f"(hi)); return r;
}
__device__ __forceinline__ void unpack2(u64 v, float& lo, float& hi) {
    asm("mov.b64 {%0, %1}, %2;" : "=f"(lo), "=f"(hi) : "l"(v));
}
__device__ __forceinline__ u64 ffma2(u64 a, u64 b, u64 c) {
    u64 d; asm("fma.rn.f32x2 %0, %1, %2, %3;" : "=l"(d) : "l"(a), "l"(b), "l"(c));
    return d;
}

// ---------------------------------------------------------------------------
// Kernel A: conv + relu + key projection, FFMA2, 256 threads/block.
// EXACT R9 version (87.3 us, at the structural LDS floor for this blocking;
// R10's vector-x variant traded occupancy for LDS and regressed).
// ---------------------------------------------------------------------------
#define TTA 256
#define SXT_STRIDE 258        // 257 cols needed, even stride
#define SPJ_STRIDE 34         // [t][d] pad; even for 8B-aligned u64 stores

__global__ void __launch_bounds__(256)
conv_scores_kernel(const float* __restrict__ x,
                   const float* __restrict__ conv_w,
                   const float* __restrict__ conv_b,
                   const float* __restrict__ keys)
{
    __shared__ __align__(16) float sbuf[TTA * SPJ_STRIDE]; // 8704 fl; sxT then proj
    __shared__ __align__(16) float sw2[HIST * DIMS];       // [h][d]
    __shared__ __align__(16) float skb[DIMS * NP];         // [d][p]
    __shared__ __align__(16) float sb[DIMS];

    const int b    = blockIdx.y;
    const int tile = blockIdx.x;
    const int tid  = threadIdx.x;
    const int wid  = tid >> 5;
    const int lane = tid & 31;
    const int dg   = wid & 3;    // per-warp d-group
    const int th   = wid >> 2;   // t-half

    // ---- stage x transposed: sxT[a][c], u = tile*8192 + c*32 + a, g = u-63
    {
        const long ubase = (long)tile * (TTA * WIN);
        const float* xb = x + (size_t)b * LL;
        for (int i = tid; i < 257 * 32; i += 256) {
            const int a = i & 31, c = i >> 5;
            const long g = ubase + (long)c * 32 + a - 63;
            sbuf[a * SXT_STRIDE + c] = (g >= 0 && g < LL) ? xb[g] : 0.f;
        }
        for (int i = tid; i < HIST * DIMS; i += 256) {
            const int d = i & 31, h = i >> 5;
            sw2[h * DIMS + d] = conv_w[d * HIST + h];
        }
        for (int i = tid; i < DIMS * NP; i += 256) skb[i] = keys[i];
        if (tid < DIMS) sb[tid] = conv_b[tid];
    }
    __syncthreads();

    const int dbase = dg * 8;
    const int tbase = th * 128 + lane;   // + 32*tt, tt=0..3

    // acc[tt][k]: f32x2 over (d=dbase+2k, d+1), init with bias
    u64 acc[4][4];
    {
        const float2* bp = (const float2*)&sb[dbase];
#pragma unroll
        for (int k = 0; k < 4; k++) {
            const float2 bv = bp[k];
            const u64 bi = pack2(bv.x, bv.y);
#pragma unroll
            for (int tt = 0; tt < 4; tt++) acc[tt][k] = bi;
        }
    }

#pragma unroll 1
    for (int half = 0; half < 2; half++) {       // h in [0,32) then [32,64)
        const int cofs = tbase + half;           // c = t + (h>>5)
#pragma unroll 4
        for (int hh = 0; hh < 32; hh++) {
            const int h = half * 32 + hh;
            const ulonglong2* wp = (const ulonglong2*)&sw2[h * DIMS + dbase];
            const ulonglong2 wa = wp[0], wb = wp[1];
            const float* xrow = &sbuf[hh * SXT_STRIDE + cofs];
            u64 xd[4];
#pragma unroll
            for (int tt = 0; tt < 4; tt++) {
                const float xv = xrow[32 * tt];
                xd[tt] = pack2(xv, xv);
            }
#pragma unroll
            for (int tt = 0; tt < 4; tt++) {
                acc[tt][0] = ffma2(xd[tt], wa.x, acc[tt][0]);
                acc[tt][1] = ffma2(xd[tt], wa.y, acc[tt][1]);
                acc[tt][2] = ffma2(xd[tt], wb.x, acc[tt][2]);
                acc[tt][3] = ffma2(xd[tt], wb.y, acc[tt][3]);
            }
        }
    }

    // ---- dump conv result (pre-relu) to sproj[t][d] (reusing sbuf)
    __syncthreads();   // all x reads done before overwrite
    {
        u64* sp64 = (u64*)sbuf;
#pragma unroll
        for (int tt = 0; tt < 4; tt++) {
            const int t = tbase + 32 * tt;
#pragma unroll
            for (int k = 0; k < 4; k++)
                sp64[(t * SPJ_STRIDE + dbase) / 2 + k] = acc[tt][k];
        }
    }
    __syncthreads();   // row t assembled from 4 warps

    // ---- projection: 128 threads, thread = (q, ph) computes 4t x 8p tile.
    if (tid < 128) {
        const int q  = tid >> 1;     // 0..63
        const int ph = tid & 1;      // p-half
        u64 pa[4][4];
#pragma unroll
        for (int i = 0; i < 4; i++)
#pragma unroll
            for (int j = 0; j < 4; j++) pa[i][j] = 0ull;

#pragma unroll 4
        for (int d = 0; d < DIMS; d++) {
            const u64* kp = (const u64*)&skb[d * NP + ph * 8];
            const u64 k0 = kp[0], k1 = kp[1], k2 = kp[2], k3 = kp[3];
#pragma unroll
            for (int i = 0; i < 4; i++) {
                const int t = q + 64 * i;
                const float oa = fmaxf(sbuf[t * SPJ_STRIDE + d], 0.f);
                const u64 o2 = pack2(oa, oa);
                pa[i][0] = ffma2(o2, k0, pa[i][0]);
                pa[i][1] = ffma2(o2, k1, pa[i][1]);
                pa[i][2] = ffma2(o2, k2, pa[i][2]);
                pa[i][3] = ffma2(o2, k3, pa[i][3]);
            }
        }

        const float L2E = 1.4426950408889634f;
#pragma unroll
        for (int i = 0; i < 4; i++) {
            const int gt = tile * TTA + q + 64 * i;
            float4* dst = (float4*)(g_scores + ((size_t)gt * BB + b) * NP + ph * 8);
#pragma unroll
            for (int v = 0; v < 2; v++) {
                float p0, p1, p2, p3;
                unpack2(pa[i][v * 2 + 0], p0, p1);
                unpack2(pa[i][v * 2 + 1], p2, p3);
                float4 o;
                o.x = fminf(fmaxf(p0, 0.f), 6.f) * L2E;
                o.y = fminf(fmaxf(p1, 0.f), 6.f) * L2E;
                o.z = fminf(fmaxf(p2, 0.f), 6.f) * L2E;
                o.w = fminf(fmaxf(p3, 0.f), 6.f) * L2E;
                dst[v] = o;
            }
        }
    }
}

// ---------------------------------------------------------------------------
// Kernel B: shfl-free chunked scan. SEGC=16, SEGW=96: depth 112, 1024 warps
// (~1.75 warps/SMSP -> co-resident chains interleave issue and hide the
// EX2/treesum latency that dominated at 1 warp/SMSP).
// ---------------------------------------------------------------------------
struct ScanState {
    float  A[NP];
    float  pp[NP];
    float  qmb[NP];
    float4 qc[4][4];
};

template<bool OUT>
__device__ __forceinline__ void scan_step(int k, int t, int b, ScanState& S,
                                          const float4* __restrict__ sp,
                                          const float* s0, const float* s1,
                                          float2* __restrict__ prm)
{
    const float L2E = 1.4426950408889634f;
    float e[NP];
#pragma unroll
    for (int i = 0; i < NP; i++)
        e[i] = ex2f(fmaf(S.pp[i], -L2E, S.qmb[i]));

    const size_t pbase = ((size_t)(t + 4) * BB + (size_t)b) * 4;
    float4 v0 = sp[pbase + 0], v1 = sp[pbase + 1],
           v2 = sp[pbase + 2], v3 = sp[pbase + 3];

#pragma unroll
    for (int i = 0; i < NP; i++)
        S.A[i] = fmaf(S.pp[i], L2E, S.A[i]);

    float ss = ((((e[0] + e[1]) + (e[2] + e[3])) + ((e[4] + e[5]) + (e[6] + e[7])))
             + (((e[8] + e[9]) + (e[10] + e[11])) + ((e[12] + e[13]) + (e[14] + e[15]))));
    float r = rcpf(ss);

    float d0, d1;
    if (OUT) {
        float a0 = 0.f, a1 = 0.f, b0 = 0.f, b1 = 0.f;
#pragma unroll
        for (int i = 0; i < NP; i += 2) {
            a0 = fmaf(e[i],     s0[i],     a0);
            b0 = fmaf(e[i + 1], s0[i + 1], b0);
            a1 = fmaf(e[i],     s1[i],     a1);
            b1 = fmaf(e[i + 1], s1[i + 1], b1);
        }
        d0 = a0 + b0; d1 = a1 + b1;
    }

#pragma unroll
    for (int i = 0; i < NP; i++) S.pp[i] = e[i] * r;

    S.qc[k][0] = v0; S.qc[k][1] = v1; S.qc[k][2] = v2; S.qc[k][3] = v3;

    const int kn = (k + 1) & 3;
#pragma unroll
    for (int j = 0; j < 4; j++) {
        const float4 n = S.qc[kn][j];
        S.qmb[j * 4 + 0] = n.x - S.A[j * 4 + 0];
        S.qmb[j * 4 + 1] = n.y - S.A[j * 4 + 1];
        S.qmb[j * 4 + 2] = n.z - S.A[j * 4 + 2];
        S.qmb[j * 4 + 3] = n.w - S.A[j * 4 + 3];
    }

    if (OUT) prm[(size_t)t * BB + b] = make_float2(d0 * r, d1 * r);
}

__global__ void __launch_bounds__(32)
scan_kernel(const float* __restrict__ avg0, const float* __restrict__ shapes)
{
    const int lane = threadIdx.x;
    const int seg  = blockIdx.x >> 2;              // 256 segments
    const int b    = (blockIdx.x & 3) * 32 + lane;

    const int s_start = seg * SEGC;
    const int t0 = (s_start >= SEGW) ? (s_start - SEGW) : 0;

    const float L2E = 1.4426950408889634f;
    const float4* sp = (const float4*)g_scores;
    float2* prm = g_params;

    ScanState S;
#pragma unroll
    for (int i = 0; i < NP; i++) {
        S.A[i]  = avg0[b * NP + i] * L2E;
        S.pp[i] = 0.f;
    }
#pragma unroll
    for (int k = 0; k < 4; k++) {
        const size_t base = ((size_t)(t0 + k) * BB + (size_t)b) * 4;
        S.qc[k][0] = sp[base + 0]; S.qc[k][1] = sp[base + 1];
        S.qc[k][2] = sp[base + 2]; S.qc[k][3] = sp[base + 3];
    }
#pragma unroll
    for (int j = 0; j < 4; j++) {
        const float4 n = S.qc[0][j];
        S.qmb[j * 4 + 0] = n.x - S.A[j * 4 + 0];
        S.qmb[j * 4 + 1] = n.y - S.A[j * 4 + 1];
        S.qmb[j * 4 + 2] = n.z - S.A[j * 4 + 2];
        S.qmb[j * 4 + 3] = n.w - S.A[j * 4 + 3];
    }

    int t = t0;
    for (; t < s_start; t += 4) {
        scan_step<false>(0, t + 0, b, S, sp, nullptr, nullptr, prm);
        scan_step<false>(1, t + 1, b, S, sp, nullptr, nullptr, prm);
        scan_step<false>(2, t + 2, b, S, sp, nullptr, nullptr, prm);
        scan_step<false>(3, t + 3, b, S, sp, nullptr, nullptr, prm);
    }

    float s0[NP], s1[NP];
#pragma unroll
    for (int i = 0; i < NP; i++) { s0[i] = shapes[i * 2]; s1[i] = shapes[i * 2 + 1]; }

    const int s_end = s_start + SEGC;
    for (; t < s_end; t += 4) {
        scan_step<true>(0, t + 0, b, S, sp, s0, s1, prm);
        scan_step<true>(1, t + 1, b, S, sp, s0, s1, prm);
        scan_step<true>(2, t + 2, b, S, sp, s0, s1, prm);
        scan_step<true>(3, t + 3, b, S, sp, s0, s1, prm);
    }
}

// ---------------------------------------------------------------------------
// Kernel C: epilogue — out = relu(offset + noise*std - x). Memory-bound.
// ---------------------------------------------------------------------------
__global__ void __launch_bounds__(256)
epilogue_kernel(const float* __restrict__ x,
                const float* __restrict__ noise,
                float* __restrict__ out)
{
    const int b  = blockIdx.y;
    const int l4 = blockIdx.x * 256 + threadIdx.x;
    const int t  = (l4 * 4) >> 5;

    const float2 pr = g_params[(size_t)t * BB + b];
    const float4 xv = ((const float4*)(x     + (size_t)b * LL))[l4];
    const float4 nv = ((const float4*)(noise + (size_t)b * LL))[l4];

    float4 o;
    o.x = fmaxf(fmaf(nv.x, pr.y, pr.x) - xv.x, 0.f);
    o.y = fmaxf(fmaf(nv.y, pr.y, pr.x) - xv.y, 0.f);
    o.z = fmaxf(fmaf(nv.z, pr.y, pr.x) - xv.z, 0.f);
    o.w = fmaxf(fmaf(nv.w, pr.y, pr.x) - xv.w, 0.f);
    ((float4*)out)[(size_t)b * (LL / 4) + l4] = o;
}

// ---------------------------------------------------------------------------
extern "C" void kernel_launch(void* const* d_in, const int* in_sizes, int n_in,
                              void* d_out, int out_size)
{
    const float* x      = (const float*)d_in[0];
    const float* avg    = (const float*)d_in[1];
    const float* noise  = (const float*)d_in[2];
    const float* conv_w = (const float*)d_in[3];
    const float* conv_b = (const float*)d_in[4];
    const float* keys   = (const float*)d_in[5];
    const float* shapes = (const float*)d_in[6];
    float* out = (float*)d_out;

    conv_scores_kernel<<<dim3(TT / TTA, BB), 256>>>(x, conv_w, conv_b, keys);
    scan_kernel<<<NSEG * 4, 32>>>(avg, shapes);
    epilogue_kernel<<<dim3(LL / 1024, BB), 256>>>(x, noise, out);
}